// round 10
// baseline (speedup 1.0000x reference)
#include <cuda_runtime.h>
#include <cuda_fp16.h>
#include <math.h>
#include <stdint.h>

#define B   64
#define T   2048
#define DL  1024
#define DE  512
#define DA  128
#define NF  32
#define KW  31
#define PADW 15
#define KC  (DE + NF)      // 544
#define CK  32             // K per chunk (two m16n8k16 k-steps)
#define NCH (KC / CK)      // 17 chunks, exact
#define TM  64             // rows per CTA tile
#define NTILE (T / TM)     // 32 tiles per batch

// dynamic smem stage layout (bytes)
#define A_STRIDE_W 20                  // words per A row (16 data + 4 pad) -> conflict-free
#define A_PLANE    (TM * A_STRIDE_W * 4)    // 5120
#define B_FRAG_BYTES (2 * 16 * 32 * 8) // 8192
#define STAGE (A_PLANE + B_FRAG_BYTES) // 13312
#define NSTAGE 3
#define DSM_BYTES (NSTAGE * STAGE)     // 39936 (< 48KB default)

// ---------------- scratch (static device memory; no allocations) -------------
__device__ __align__(16) float g_qq[B][DA];           // query proj + bq + bm
__device__ __align__(16) float g_conv[B][T][NF];      // location conv output
__device__ __align__(16) float g_e[B][T];             // energies
__device__ __align__(16) uint2 g_Bfrag[NCH * 2 * 16 * 32];  // Wcat fp16 fragments
__device__ __align__(16) float g_pctx[B * NTILE * DE];  // per-tile partial contexts
__device__ __align__(16) float2 g_ms[B * NTILE];        // per-tile (max, sumexp)

// ---------------- helpers ----------------------------------------------------
__device__ __forceinline__ unsigned smem_u32(const void* p) {
    return (unsigned)__cvta_generic_to_shared(p);
}
__device__ __forceinline__ void cpasync16(void* smem, const void* gmem) {
    asm volatile("cp.async.cg.shared.global [%0], [%1], 16;\n"
                 :: "r"(smem_u32(smem)), "l"(gmem));
}
__device__ __forceinline__ void mma_f16(float* c, const unsigned* a, unsigned b0, unsigned b1) {
    asm volatile(
        "mma.sync.aligned.m16n8k16.row.col.f32.f16.f16.f32 "
        "{%0,%1,%2,%3}, {%4,%5,%6,%7}, {%8,%9}, {%0,%1,%2,%3};\n"
        : "+f"(c[0]), "+f"(c[1]), "+f"(c[2]), "+f"(c[3])
        : "r"(a[0]), "r"(a[1]), "r"(a[2]), "r"(a[3]), "r"(b0), "r"(b1));
}
__device__ __forceinline__ unsigned pack_h2(float a0, float a1) {
    __half2 h = __floats2half2_rn(a0, a1);
    return *reinterpret_cast<unsigned*>(&h);
}

// ---------------- K0a: qq[b][a] = query[b]·Wq[a] + bq[a] + bm[a] --------------
__global__ void k_qq(const float* __restrict__ query, const float* __restrict__ Wq,
                     const float* __restrict__ bq, const float* __restrict__ bm) {
    __shared__ float4 sq[DL / 4];
    int b = blockIdx.x, tid = threadIdx.x;
    for (int i = tid; i < DL / 4; i += 128)
        sq[i] = ((const float4*)(query + (size_t)b * DL))[i];
    __syncthreads();
    int w = tid >> 5, lane = tid & 31;
    int a0 = blockIdx.y * 32 + w * 8;
    #pragma unroll
    for (int j = 0; j < 8; j++) {
        int a = a0 + j;
        const float4* wr = (const float4*)(Wq + (size_t)a * DL);
        float s = 0.f;
        #pragma unroll
        for (int k = 0; k < DL / 128; k++) {
            float4 q4 = sq[lane + 32 * k];
            float4 w4 = wr[lane + 32 * k];
            s += q4.x * w4.x + q4.y * w4.y + q4.z * w4.z + q4.w * w4.w;
        }
        #pragma unroll
        for (int o = 16; o; o >>= 1) s += __shfl_xor_sync(0xffffffffu, s, o);
        if (lane == 0) g_qq[b][a] = s + bq[a] + bm[a];
    }
}

// ---------------- K0b: Wcat -> fp16 mma fragments ----------------------------
// Layout keyed for uint4 loads in k_main: [(ch, s, wN, lane, ntl)] so one
// thread's 4 nt values are 2 adjacent uint4s.
__global__ void k_prepB(const float* __restrict__ Wm, const float* __restrict__ Wloc) {
    int idx = blockIdx.x * 256 + threadIdx.x;        // one per (ch, s, nt, lane)
    if (idx >= NCH * 2 * 16 * 32) return;
    int lane = idx & 31, nt = (idx >> 5) & 15, s = (idx >> 9) & 1, ch = idx >> 10;
    int g = lane >> 2, t = lane & 3;
    int n = nt * 8 + g;
    int k0 = ch * CK + s * 16;
    float v[4];
    #pragma unroll
    for (int j = 0; j < 4; j++) {
        int k = k0 + ((j >> 1) ? (2 * t + 8) : (2 * t)) + (j & 1);
        v[j] = (k < DE) ? Wm[(size_t)n * DE + k] : Wloc[n * NF + (k - DE)];
    }
    int wN = nt >> 2, ntl = nt & 3;
    int nidx = ((((ch * 2 + s) * 4 + wN) * 32 + lane) * 4) + ntl;
    g_Bfrag[nidx] = make_uint2(pack_h2(v[0], v[1]), pack_h2(v[2], v[3]));
}

// ---------------- K2: location conv (same padding), [B][T][NF] ----------------
__global__ void k_conv(const float* __restrict__ aw, const float* __restrict__ Wconv) {
    __shared__ float s_aw[2][128 + KW - 1];
    __shared__ float s_w[NF * 2 * KW];
    int b = blockIdx.x, t0 = blockIdx.y * 128, tid = threadIdx.x;  // 128 threads
    for (int i = tid; i < NF * 2 * KW; i += 128) s_w[i] = Wconv[i];
    for (int c = 0; c < 2; c++)
        for (int i = tid; i < 128 + KW - 1; i += 128) {
            int t = t0 - PADW + i;
            s_aw[c][i] = (t >= 0 && t < T) ? aw[((size_t)b * 2 + c) * T + t] : 0.f;
        }
    __syncthreads();
    float out[NF];
    #pragma unroll 4
    for (int f = 0; f < NF; f++) {
        float acc = 0.f;
        #pragma unroll
        for (int c = 0; c < 2; c++)
            #pragma unroll
            for (int k = 0; k < KW; k++)
                acc += s_aw[c][tid + k] * s_w[(f * 2 + c) * KW + k];
        out[f] = acc;
    }
    float4* dst = (float4*)&g_conv[b][t0 + tid][0];
    #pragma unroll
    for (int j = 0; j < NF / 4; j++)
        dst[j] = make_float4(out[4 * j], out[4 * j + 1], out[4 * j + 2], out[4 * j + 3]);
}

// ---------------- K3: fused S=[mem|conv]·Wcat -> tanh -> e -> flash partial ---
// CTA = one (b, 64-t tile): 64x128x544 fp16 GEMM + per-tile softmax partials +
// partial context GEMV. 256 threads, 8 warps (2M x 4N), 4 CTAs/SM.
__global__ __launch_bounds__(256, 4) void k_main(const float* __restrict__ mem,
                                                 const float* __restrict__ Wv,
                                                 const float* __restrict__ bv) {
    extern __shared__ __align__(16) char dsm[];
    __shared__ float s_qq[DA], s_wv[DA], s_esum[TM], sp[TM];
    __shared__ float s_ml;

    int tid = threadIdx.x, lane = tid & 31, w = tid >> 5;
    int g = lane >> 2, t4 = lane & 3;
    int wM = w & 1, wN = w >> 1;                     // 2 x 4 warps
    int tx = blockIdx.x, b = blockIdx.y;
    int t0 = tx * TM;
    float bv0 = bv[0];

    if (tid < DA) { s_qq[tid] = g_qq[b][tid]; s_wv[tid] = Wv[tid]; }
    if (tid >= 128 && tid < 128 + TM) s_esum[tid - 128] = 0.f;

    const float* memB = mem + ((size_t)b * T + t0) * DE;
    int arow = tid >> 2, aq = tid & 3;               // A slot: 8 cols per thread

    float acc[2][4][4];
    #pragma unroll
    for (int mt = 0; mt < 2; mt++)
        #pragma unroll
        for (int nt = 0; nt < 4; nt++)
            #pragma unroll
            for (int j = 0; j < 4; j++) acc[mt][nt][j] = 0.f;

    // ---- helpers ----
    auto ldA = [&](int ch, float4* v) {
        int kk0 = ch * CK + aq * 8;
        const float4* src = (kk0 < DE)
            ? (const float4*)(memB + (size_t)arow * DE + kk0)
            : (const float4*)(&g_conv[b][t0 + arow][kk0 - DE]);
        v[0] = src[0]; v[1] = src[1];
    };
    auto stA = [&](int buf, const float4* v) {
        unsigned* st = (unsigned*)(dsm + buf * STAGE);
        unsigned h0 = pack_h2(v[0].x, v[0].y), h1 = pack_h2(v[0].z, v[0].w);
        unsigned h2 = pack_h2(v[1].x, v[1].y), h3 = pack_h2(v[1].z, v[1].w);
        *(uint4*)(st + arow * A_STRIDE_W + aq * 4) = make_uint4(h0, h1, h2, h3);
    };
    auto ldB = [&](int ch, int buf) {
        char* bb = dsm + buf * STAGE + A_PLANE;
        const char* src = (const char*)&g_Bfrag[ch * 1024];
        cpasync16(bb + tid * 16, src + tid * 16);
        cpasync16(bb + (tid + 256) * 16, src + (tid + 256) * 16);
        asm volatile("cp.async.commit_group;\n");
    };

    // ---- prologue: fill stages 0 and 1 ----
    {
        float4 v0[2], v1[2];
        ldA(0, v0);
        ldA(1, v1);
        ldB(0, 0);
        ldB(1, 1);
        stA(0, v0);
        stA(1, v1);
        asm volatile("cp.async.wait_group 0;\n");
    }
    __syncthreads();

    // ---- main loop: stage cur ready; prefetch ch+2 into (cur+2)%3 ----
    int cur = 0;
    for (int ch = 0; ch < NCH; ch++) {
        bool pre = (ch + 2) < NCH;
        int nxt = cur + 2; if (nxt >= NSTAGE) nxt -= NSTAGE;
        float4 v[2];
        if (pre) { ldA(ch + 2, v); ldB(ch + 2, nxt); }

        const unsigned* As = (const unsigned*)(dsm + cur * STAGE);
        const uint4*    Bf4 = (const uint4*)(dsm + cur * STAGE + A_PLANE);

        #pragma unroll
        for (int s = 0; s < 2; s++) {
            unsigned af[2][4];
            #pragma unroll
            for (int mt = 0; mt < 2; mt++) {
                int r0 = (wM * 32 + mt * 16 + g) * A_STRIDE_W + s * 8 + t4;
                int r8 = r0 + 8 * A_STRIDE_W;
                af[mt][0] = As[r0];     af[mt][1] = As[r8];
                af[mt][2] = As[r0 + 4]; af[mt][3] = As[r8 + 4];
            }
            int bbase = ((s * 4 + wN) * 32 + lane) * 2;
            uint4 b01 = Bf4[bbase];
            uint4 b23 = Bf4[bbase + 1];
            #pragma unroll
            for (int mt = 0; mt < 2; mt++) {
                mma_f16(acc[mt][0], af[mt], b01.x, b01.y);
                mma_f16(acc[mt][1], af[mt], b01.z, b01.w);
                mma_f16(acc[mt][2], af[mt], b23.x, b23.y);
                mma_f16(acc[mt][3], af[mt], b23.z, b23.w);
            }
        }

        if (pre) {
            stA(nxt, v);
            asm volatile("cp.async.wait_group 1;\n");
        } else {
            asm volatile("cp.async.wait_group 0;\n");
        }
        __syncthreads();
        cur = cur + 1 == NSTAGE ? 0 : cur + 1;
    }

    // ---- e[t] = bv + sum_a Wv[a]*tanh(acc + qq[a]) ----
    #pragma unroll
    for (int mt = 0; mt < 2; mt++) {
        #pragma unroll
        for (int half = 0; half < 2; half++) {
            int rloc = wM * 32 + mt * 16 + g + 8 * half;
            float p = 0.f;
            #pragma unroll
            for (int nt = 0; nt < 4; nt++) {
                int c0 = wN * 32 + nt * 8 + 2 * t4;
                float x0 = acc[mt][nt][2 * half + 0] + s_qq[c0];
                float x1 = acc[mt][nt][2 * half + 1] + s_qq[c0 + 1];
                float e0 = __expf(2.f * x0), e1 = __expf(2.f * x1);
                p += s_wv[c0]     * (1.f - __fdividef(2.f, e0 + 1.f));
                p += s_wv[c0 + 1] * (1.f - __fdividef(2.f, e1 + 1.f));
            }
            p += __shfl_xor_sync(0xffffffffu, p, 1);
            p += __shfl_xor_sync(0xffffffffu, p, 2);
            if (t4 == 0) atomicAdd(&s_esum[rloc], p);
        }
    }
    __syncthreads();

    // ---- flash partials: m_l, p_t, s_l, partial ctx ----
    if (tid < 32) {
        float m = fmaxf(s_esum[tid], s_esum[tid + 32]);
        #pragma unroll
        for (int o = 16; o; o >>= 1) m = fmaxf(m, __shfl_xor_sync(0xffffffffu, m, o));
        if (tid == 0) s_ml = m;
    }
    if (tid < TM) g_e[b][t0 + tid] = s_esum[tid] + bv0;
    __syncthreads();
    if (tid < TM) sp[tid] = __expf(s_esum[tid] - s_ml);
    __syncthreads();
    if (tid < 32) {
        float ssum = sp[tid] + sp[tid + 32];
        #pragma unroll
        for (int o = 16; o; o >>= 1) ssum += __shfl_xor_sync(0xffffffffu, ssum, o);
        if (tid == 0) g_ms[b * NTILE + tx] = make_float2(s_ml, ssum);
    }
    // partial context: pctx[d] = sum_t sp[t] * mem[t][d]  (tile is L2-hot)
    {
        const float2* mp2 = (const float2*)memB + tid;    // d = 2*tid, 2*tid+1
        float c0 = 0.f, c1 = 0.f;
        #pragma unroll 8
        for (int t = 0; t < TM; t++) {
            float wt = sp[t];
            float2 m2 = mp2[(size_t)t * (DE / 2)];
            c0 += wt * m2.x;
            c1 += wt * m2.y;
        }
        *(float2*)&g_pctx[((size_t)b * NTILE + tx) * DE + 2 * tid] = make_float2(c0, c1);
    }
}

// ---------------- K4: blocks 0..63 softmax -> out_w; 64..127 combine ctx -----
__global__ __launch_bounds__(512) void k_fin(float* __restrict__ out_w,
                                             float* __restrict__ out_ctx) {
    __shared__ float red[512];
    int tid = threadIdx.x;
    if (blockIdx.x < B) {
        int b = blockIdx.x;
        float v[4];
        float m = -1e30f;
        #pragma unroll
        for (int j = 0; j < 4; j++) { v[j] = g_e[b][tid + 512 * j]; m = fmaxf(m, v[j]); }
        red[tid] = m; __syncthreads();
        for (int s = 256; s; s >>= 1) { if (tid < s) red[tid] = fmaxf(red[tid], red[tid + s]); __syncthreads(); }
        m = red[0]; __syncthreads();
        float sum = 0.f;
        #pragma unroll
        for (int j = 0; j < 4; j++) { v[j] = expf(v[j] - m); sum += v[j]; }
        red[tid] = sum; __syncthreads();
        for (int s = 256; s; s >>= 1) { if (tid < s) red[tid] += red[tid + s]; __syncthreads(); }
        float inv = 1.f / red[0];
        #pragma unroll
        for (int j = 0; j < 4; j++) out_w[(size_t)b * T + tid + 512 * j] = v[j] * inv;
    } else {
        int b = blockIdx.x - B;
        __shared__ float sm[NTILE], ss[NTILE];
        if (tid < NTILE) {
            float2 v = g_ms[b * NTILE + tid];
            sm[tid] = v.x; ss[tid] = v.y;
        }
        __syncthreads();
        float mg = -1e30f;
        #pragma unroll
        for (int l = 0; l < NTILE; l++) mg = fmaxf(mg, sm[l]);
        float Sg = 0.f;
        float sc[NTILE];
        #pragma unroll
        for (int l = 0; l < NTILE; l++) { sc[l] = expf(sm[l] - mg); Sg += ss[l] * sc[l]; }
        float invS = 1.f / Sg;
        float acc = 0.f;
        #pragma unroll
        for (int l = 0; l < NTILE; l++)
            acc += sc[l] * g_pctx[((size_t)b * NTILE + l) * DE + tid];
        out_ctx[(size_t)b * DE + tid] = acc * invS;
    }
}

// ---------------- launch ------------------------------------------------------
extern "C" void kernel_launch(void* const* d_in, const int* in_sizes, int n_in,
                              void* d_out, int out_size) {
    const float* query  = (const float*)d_in[0];
    const float* memory = (const float*)d_in[1];
    const float* aw     = (const float*)d_in[2];
    const float* Wq     = (const float*)d_in[3];
    const float* bq     = (const float*)d_in[4];
    const float* Wm     = (const float*)d_in[5];
    const float* bm     = (const float*)d_in[6];
    const float* Wconv  = (const float*)d_in[7];
    const float* Wloc   = (const float*)d_in[8];
    const float* Wv     = (const float*)d_in[9];
    const float* bv     = (const float*)d_in[10];

    float* out_ctx = (float*)d_out;            // [B][DE]
    float* out_w   = (float*)d_out + B * DE;   // [B][T]

    k_qq   <<<dim3(B, 4), 128>>>(query, Wq, bq, bm);
    k_prepB<<<(NCH * 2 * 16 * 32 + 255) / 256, 256>>>(Wm, Wloc);
    k_conv <<<dim3(B, T / 128), 128>>>(aw, Wconv);
    k_main <<<dim3(NTILE, B), 256, DSM_BYTES>>>(memory, Wv, bv);
    k_fin  <<<2 * B, 512>>>(out_w, out_ctx);
}

// round 14
// speedup vs baseline: 1.2856x; 1.2856x over previous
#include <cuda_runtime.h>
#include <cuda_fp16.h>
#include <math.h>
#include <stdint.h>

#define B   64
#define T   2048
#define DL  1024
#define DE  512
#define DA  128
#define NF  32
#define KW  31
#define PADW 15
#define KC  (DE + NF)      // 544
#define CK  32             // K per chunk (two m16n8k16 k-steps)
#define NCH (KC / CK)      // 17 chunks, exact
#define TM  64             // rows per CTA tile
#define NTILE (T / TM)     // 32 tiles per batch

// dynamic smem stage layout (bytes)
#define A_STRIDE_W 20                  // words per A row (16 data + 4 pad) -> conflict-free
#define A_PLANE    (TM * A_STRIDE_W * 4)    // 5120
#define B_FRAG_BYTES (2 * 16 * 32 * 8) // 8192
#define STAGE (A_PLANE + B_FRAG_BYTES) // 13312
#define NSTAGE 3
#define DSM_BYTES (NSTAGE * STAGE)     // 39936 (< 48KB default)

// ---------------- scratch (static device memory; no allocations) -------------
__device__ __align__(16) float g_qq[B][DA];           // query proj + bq + bm
__device__ __align__(16) float g_conv[B][T][NF];      // location conv output
__device__ __align__(16) float g_e[B][T];             // energies
__device__ __align__(16) uint2 g_Bfrag[NCH * 2 * 16 * 32];  // Wcat fp16 fragments
__device__ __align__(16) float g_pctx[B * NTILE * DE];  // per-tile partial contexts
__device__ __align__(16) float2 g_ms[B * NTILE];        // per-tile (max, sumexp)

// ---------------- helpers ----------------------------------------------------
__device__ __forceinline__ unsigned smem_u32(const void* p) {
    return (unsigned)__cvta_generic_to_shared(p);
}
__device__ __forceinline__ void cpasync16(void* smem, const void* gmem) {
    asm volatile("cp.async.cg.shared.global [%0], [%1], 16;\n"
                 :: "r"(smem_u32(smem)), "l"(gmem));
}
__device__ __forceinline__ void mma_f16(float* c, const unsigned* a, unsigned b0, unsigned b1) {
    asm volatile(
        "mma.sync.aligned.m16n8k16.row.col.f32.f16.f16.f32 "
        "{%0,%1,%2,%3}, {%4,%5,%6,%7}, {%8,%9}, {%0,%1,%2,%3};\n"
        : "+f"(c[0]), "+f"(c[1]), "+f"(c[2]), "+f"(c[3])
        : "r"(a[0]), "r"(a[1]), "r"(a[2]), "r"(a[3]), "r"(b0), "r"(b1));
}
__device__ __forceinline__ unsigned pack_h2(float a0, float a1) {
    __half2 h = __floats2half2_rn(a0, a1);
    return *reinterpret_cast<unsigned*>(&h);
}

// ---------------- K0a: qq[b][a] = query[b]·Wq[a] + bq[a] + bm[a] --------------
__global__ void k_qq(const float* __restrict__ query, const float* __restrict__ Wq,
                     const float* __restrict__ bq, const float* __restrict__ bm) {
    __shared__ float4 sq[DL / 4];
    int b = blockIdx.x, tid = threadIdx.x;
    for (int i = tid; i < DL / 4; i += 128)
        sq[i] = ((const float4*)(query + (size_t)b * DL))[i];
    __syncthreads();
    int w = tid >> 5, lane = tid & 31;
    int a0 = blockIdx.y * 32 + w * 8;
    #pragma unroll
    for (int j = 0; j < 8; j++) {
        int a = a0 + j;
        const float4* wr = (const float4*)(Wq + (size_t)a * DL);
        float s = 0.f;
        #pragma unroll
        for (int k = 0; k < DL / 128; k++) {
            float4 q4 = sq[lane + 32 * k];
            float4 w4 = wr[lane + 32 * k];
            s += q4.x * w4.x + q4.y * w4.y + q4.z * w4.z + q4.w * w4.w;
        }
        #pragma unroll
        for (int o = 16; o; o >>= 1) s += __shfl_xor_sync(0xffffffffu, s, o);
        if (lane == 0) g_qq[b][a] = s + bq[a] + bm[a];
    }
}

// ---------------- K0b: Wcat -> fp16 mma fragments ----------------------------
// Layout [(ch, s, nt, lane)] -> uint2; k_main reads with 8B lane stride
// (conflict-free LDS.64).
__global__ void k_prepB(const float* __restrict__ Wm, const float* __restrict__ Wloc) {
    int idx = blockIdx.x * 256 + threadIdx.x;        // one per (ch, s, nt, lane)
    if (idx >= NCH * 2 * 16 * 32) return;
    int lane = idx & 31, nt = (idx >> 5) & 15, s = (idx >> 9) & 1, ch = idx >> 10;
    int g = lane >> 2, t = lane & 3;
    int n = nt * 8 + g;
    int k0 = ch * CK + s * 16;
    float v[4];
    #pragma unroll
    for (int j = 0; j < 4; j++) {
        int k = k0 + ((j >> 1) ? (2 * t + 8) : (2 * t)) + (j & 1);
        v[j] = (k < DE) ? Wm[(size_t)n * DE + k] : Wloc[n * NF + (k - DE)];
    }
    g_Bfrag[idx] = make_uint2(pack_h2(v[0], v[1]), pack_h2(v[2], v[3]));
}

// ---------------- K2: location conv (same padding), [B][T][NF] ----------------
__global__ void k_conv(const float* __restrict__ aw, const float* __restrict__ Wconv) {
    __shared__ float s_aw[2][128 + KW - 1];
    __shared__ float s_w[NF * 2 * KW];
    int b = blockIdx.x, t0 = blockIdx.y * 128, tid = threadIdx.x;  // 128 threads
    for (int i = tid; i < NF * 2 * KW; i += 128) s_w[i] = Wconv[i];
    for (int c = 0; c < 2; c++)
        for (int i = tid; i < 128 + KW - 1; i += 128) {
            int t = t0 - PADW + i;
            s_aw[c][i] = (t >= 0 && t < T) ? aw[((size_t)b * 2 + c) * T + t] : 0.f;
        }
    __syncthreads();
    float out[NF];
    #pragma unroll 4
    for (int f = 0; f < NF; f++) {
        float acc = 0.f;
        #pragma unroll
        for (int c = 0; c < 2; c++)
            #pragma unroll
            for (int k = 0; k < KW; k++)
                acc += s_aw[c][tid + k] * s_w[(f * 2 + c) * KW + k];
        out[f] = acc;
    }
    float4* dst = (float4*)&g_conv[b][t0 + tid][0];
    #pragma unroll
    for (int j = 0; j < NF / 4; j++)
        dst[j] = make_float4(out[4 * j], out[4 * j + 1], out[4 * j + 2], out[4 * j + 3]);
}

// ---------------- K3: fused S=[mem|conv]·Wcat -> tanh -> e -> flash partial ---
// CTA = one (b, 64-t tile): 64x128x544 fp16 GEMM + per-tile softmax partials +
// partial context GEMV. 256 threads, 8 warps (2M x 4N), 3 CTAs/SM.
// A fragments loaded via ldmatrix.x4 (4 LDSM/chunk vs 16 LDS.32).
__global__ __launch_bounds__(256, 3) void k_main(const float* __restrict__ mem,
                                                 const float* __restrict__ Wv,
                                                 const float* __restrict__ bv) {
    extern __shared__ __align__(16) char dsm[];
    __shared__ float s_qq[DA], s_wv[DA], s_esum[TM], sp[TM];
    __shared__ float s_ml;

    int tid = threadIdx.x, lane = tid & 31, w = tid >> 5;
    int g = lane >> 2, t4 = lane & 3;
    int wM = w & 1, wN = w >> 1;                     // 2 x 4 warps
    int tx = blockIdx.x, b = blockIdx.y;
    int t0 = tx * TM;
    float bv0 = bv[0];

    if (tid < DA) { s_qq[tid] = g_qq[b][tid]; s_wv[tid] = Wv[tid]; }
    if (tid >= 128 && tid < 128 + TM) s_esum[tid - 128] = 0.f;

    const float* memB = mem + ((size_t)b * T + t0) * DE;
    int arow = tid >> 2, aq = tid & 3;               // A slot: 8 cols per thread

    // ldmatrix row pointer pieces (per lane, per mt): quadrant layout
    int lmq = lane >> 3, lmr = lane & 7;
    int lmrow_base = wM * 32 + lmr + (lmq & 1) * 8;  // + mt*16
    int lmword = (lmq >> 1) * 4;                     // + s*8

    float acc[2][4][4];
    #pragma unroll
    for (int mt = 0; mt < 2; mt++)
        #pragma unroll
        for (int nt = 0; nt < 4; nt++)
            #pragma unroll
            for (int j = 0; j < 4; j++) acc[mt][nt][j] = 0.f;

    // ---- helpers ----
    auto ldA = [&](int ch, float4* v) {
        int kk0 = ch * CK + aq * 8;
        const float4* src = (kk0 < DE)
            ? (const float4*)(memB + (size_t)arow * DE + kk0)
            : (const float4*)(&g_conv[b][t0 + arow][kk0 - DE]);
        v[0] = src[0]; v[1] = src[1];
    };
    auto stA = [&](int buf, const float4* v) {
        unsigned* st = (unsigned*)(dsm + buf * STAGE);
        unsigned h0 = pack_h2(v[0].x, v[0].y), h1 = pack_h2(v[0].z, v[0].w);
        unsigned h2 = pack_h2(v[1].x, v[1].y), h3 = pack_h2(v[1].z, v[1].w);
        *(uint4*)(st + arow * A_STRIDE_W + aq * 4) = make_uint4(h0, h1, h2, h3);
    };
    auto ldB = [&](int ch, int buf) {
        char* bb = dsm + buf * STAGE + A_PLANE;
        const char* src = (const char*)&g_Bfrag[ch * 1024];
        cpasync16(bb + tid * 16, src + tid * 16);
        cpasync16(bb + (tid + 256) * 16, src + (tid + 256) * 16);
        asm volatile("cp.async.commit_group;\n");
    };

    // ---- prologue: fill stages 0 and 1 ----
    {
        float4 v0[2], v1[2];
        ldA(0, v0);
        ldA(1, v1);
        ldB(0, 0);
        ldB(1, 1);
        stA(0, v0);
        stA(1, v1);
        asm volatile("cp.async.wait_group 0;\n");
    }
    __syncthreads();

    // ---- main loop: stage cur ready; prefetch ch+2 into (cur+2)%3 ----
    int cur = 0;
    for (int ch = 0; ch < NCH; ch++) {
        bool pre = (ch + 2) < NCH;
        int nxt = cur + 2; if (nxt >= NSTAGE) nxt -= NSTAGE;
        float4 v[2];
        if (pre) { ldA(ch + 2, v); ldB(ch + 2, nxt); }

        unsigned abase = smem_u32(dsm + cur * STAGE);
        const uint2* Bf = (const uint2*)(dsm + cur * STAGE + A_PLANE);

        #pragma unroll
        for (int s = 0; s < 2; s++) {
            unsigned af[2][4];
            #pragma unroll
            for (int mt = 0; mt < 2; mt++) {
                unsigned addr = abase +
                    (((lmrow_base + mt * 16) * A_STRIDE_W) + (s * 8 + lmword)) * 4;
                asm volatile(
                    "ldmatrix.sync.aligned.m8n8.x4.shared.b16 {%0,%1,%2,%3}, [%4];"
                    : "=r"(af[mt][0]), "=r"(af[mt][1]), "=r"(af[mt][2]), "=r"(af[mt][3])
                    : "r"(addr));
            }
            #pragma unroll
            for (int nt = 0; nt < 4; nt++) {
                uint2 bf = Bf[(s * 16 + wN * 4 + nt) * 32 + lane];
                #pragma unroll
                for (int mt = 0; mt < 2; mt++)
                    mma_f16(acc[mt][nt], af[mt], bf.x, bf.y);
            }
        }

        if (pre) {
            stA(nxt, v);
            asm volatile("cp.async.wait_group 1;\n");
        } else {
            asm volatile("cp.async.wait_group 0;\n");
        }
        __syncthreads();
        cur = cur + 1 == NSTAGE ? 0 : cur + 1;
    }

    // ---- e[t] = bv + sum_a Wv[a]*tanh(acc + qq[a]) ----
    #pragma unroll
    for (int mt = 0; mt < 2; mt++) {
        #pragma unroll
        for (int half = 0; half < 2; half++) {
            int rloc = wM * 32 + mt * 16 + g + 8 * half;
            float p = 0.f;
            #pragma unroll
            for (int nt = 0; nt < 4; nt++) {
                int c0 = wN * 32 + nt * 8 + 2 * t4;
                float x0 = acc[mt][nt][2 * half + 0] + s_qq[c0];
                float x1 = acc[mt][nt][2 * half + 1] + s_qq[c0 + 1];
                float e0 = __expf(2.f * x0), e1 = __expf(2.f * x1);
                p += s_wv[c0]     * (1.f - __fdividef(2.f, e0 + 1.f));
                p += s_wv[c0 + 1] * (1.f - __fdividef(2.f, e1 + 1.f));
            }
            p += __shfl_xor_sync(0xffffffffu, p, 1);
            p += __shfl_xor_sync(0xffffffffu, p, 2);
            if (t4 == 0) atomicAdd(&s_esum[rloc], p);
        }
    }
    __syncthreads();

    // ---- flash partials: m_l, p_t, s_l, partial ctx ----
    if (tid < 32) {
        float m = fmaxf(s_esum[tid], s_esum[tid + 32]);
        #pragma unroll
        for (int o = 16; o; o >>= 1) m = fmaxf(m, __shfl_xor_sync(0xffffffffu, m, o));
        if (tid == 0) s_ml = m;
    }
    if (tid < TM) g_e[b][t0 + tid] = s_esum[tid] + bv0;
    __syncthreads();
    if (tid < TM) sp[tid] = __expf(s_esum[tid] - s_ml);
    __syncthreads();
    if (tid < 32) {
        float ssum = sp[tid] + sp[tid + 32];
        #pragma unroll
        for (int o = 16; o; o >>= 1) ssum += __shfl_xor_sync(0xffffffffu, ssum, o);
        if (tid == 0) g_ms[b * NTILE + tx] = make_float2(s_ml, ssum);
    }
    // partial context: pctx[d] = sum_t sp[t] * mem[t][d]  (tile is L2-hot)
    {
        const float2* mp2 = (const float2*)memB + tid;    // d = 2*tid, 2*tid+1
        float c0 = 0.f, c1 = 0.f;
        #pragma unroll 8
        for (int t = 0; t < TM; t++) {
            float wt = sp[t];
            float2 m2 = mp2[(size_t)t * (DE / 2)];
            c0 += wt * m2.x;
            c1 += wt * m2.y;
        }
        *(float2*)&g_pctx[((size_t)b * NTILE + tx) * DE + 2 * tid] = make_float2(c0, c1);
    }
}

// ---------------- K4: blocks 0..63 softmax -> out_w; 64..127 combine ctx -----
__global__ __launch_bounds__(512) void k_fin(float* __restrict__ out_w,
                                             float* __restrict__ out_ctx) {
    __shared__ float red[512];
    int tid = threadIdx.x;
    if (blockIdx.x < B) {
        int b = blockIdx.x;
        float v[4];
        float m = -1e30f;
        #pragma unroll
        for (int j = 0; j < 4; j++) { v[j] = g_e[b][tid + 512 * j]; m = fmaxf(m, v[j]); }
        red[tid] = m; __syncthreads();
        for (int s = 256; s; s >>= 1) { if (tid < s) red[tid] = fmaxf(red[tid], red[tid + s]); __syncthreads(); }
        m = red[0]; __syncthreads();
        float sum = 0.f;
        #pragma unroll
        for (int j = 0; j < 4; j++) { v[j] = expf(v[j] - m); sum += v[j]; }
        red[tid] = sum; __syncthreads();
        for (int s = 256; s; s >>= 1) { if (tid < s) red[tid] += red[tid + s]; __syncthreads(); }
        float inv = 1.f / red[0];
        #pragma unroll
        for (int j = 0; j < 4; j++) out_w[(size_t)b * T + tid + 512 * j] = v[j] * inv;
    } else {
        int b = blockIdx.x - B;
        __shared__ float sm[NTILE], ss[NTILE];
        if (tid < NTILE) {
            float2 v = g_ms[b * NTILE + tid];
            sm[tid] = v.x; ss[tid] = v.y;
        }
        __syncthreads();
        float mg = -1e30f;
        #pragma unroll
        for (int l = 0; l < NTILE; l++) mg = fmaxf(mg, sm[l]);
        float Sg = 0.f;
        float sc[NTILE];
        #pragma unroll
        for (int l = 0; l < NTILE; l++) { sc[l] = expf(sm[l] - mg); Sg += ss[l] * sc[l]; }
        float invS = 1.f / Sg;
        float acc = 0.f;
        #pragma unroll
        for (int l = 0; l < NTILE; l++)
            acc += sc[l] * g_pctx[((size_t)b * NTILE + l) * DE + tid];
        out_ctx[(size_t)b * DE + tid] = acc * invS;
    }
}

// ---------------- launch ------------------------------------------------------
extern "C" void kernel_launch(void* const* d_in, const int* in_sizes, int n_in,
                              void* d_out, int out_size) {
    const float* query  = (const float*)d_in[0];
    const float* memory = (const float*)d_in[1];
    const float* aw     = (const float*)d_in[2];
    const float* Wq     = (const float*)d_in[3];
    const float* bq     = (const float*)d_in[4];
    const float* Wm     = (const float*)d_in[5];
    const float* bm     = (const float*)d_in[6];
    const float* Wconv  = (const float*)d_in[7];
    const float* Wloc   = (const float*)d_in[8];
    const float* Wv     = (const float*)d_in[9];
    const float* bv     = (const float*)d_in[10];

    float* out_ctx = (float*)d_out;            // [B][DE]
    float* out_w   = (float*)d_out + B * DE;   // [B][T]

    k_qq   <<<dim3(B, 4), 128>>>(query, Wq, bq, bm);
    k_prepB<<<(NCH * 2 * 16 * 32 + 255) / 256, 256>>>(Wm, Wloc);
    k_conv <<<dim3(B, T / 128), 128>>>(aw, Wconv);
    k_main <<<dim3(NTILE, B), 256, DSM_BYTES>>>(memory, Wv, bv);
    k_fin  <<<2 * B, 512>>>(out_w, out_ctx);
}

// round 16
// speedup vs baseline: 1.4359x; 1.1169x over previous
#include <cuda_runtime.h>
#include <cuda_fp16.h>
#include <math.h>
#include <stdint.h>

#define B   64
#define T   2048
#define DL  1024
#define DE  512
#define DA  128
#define NF  32
#define KW  31
#define PADW 15
#define KC  (DE + NF)      // 544
#define CK  32             // K per chunk (two m16n8k16 k-steps)
#define NCHP 18            // padded chunks (544 -> 576, chunk 17 = zeros)
#define NITER 9            // 2 chunks per iteration
#define TM  64             // rows per CTA tile
#define NTILE (T / TM)     // 32 tiles per batch

// dynamic smem stage layout (bytes)
#define A_STRIDE_W 20                  // words per A row (16 data + 4 pad) -> conflict-free
#define A_PLANE    (TM * A_STRIDE_W * 4)    // 5120
#define B_FRAG_BYTES (2 * 16 * 32 * 8) // 8192
#define STAGE (A_PLANE + B_FRAG_BYTES) // 13312
#define NSTAGE 4
#define DSM_BYTES (NSTAGE * STAGE)     // 53248 (opt-in)

// ---------------- scratch (static device memory; no allocations) -------------
__device__ __align__(16) float g_qq[B][DA];           // query proj + bq + bm
__device__ __align__(16) float g_conv[B][T][NF];      // location conv output
__device__ __align__(16) float g_e[B][T];             // energies
__device__ __align__(16) uint2 g_Bfrag[NCHP * 2 * 16 * 32];  // Wcat fp16 fragments
__device__ __align__(16) float g_pctx[B * NTILE * DE];  // per-tile partial contexts
__device__ __align__(16) float2 g_ms[B * NTILE];        // per-tile (max, sumexp)

// ---------------- helpers ----------------------------------------------------
__device__ __forceinline__ unsigned smem_u32(const void* p) {
    return (unsigned)__cvta_generic_to_shared(p);
}
__device__ __forceinline__ void cpasync16(void* smem, const void* gmem) {
    asm volatile("cp.async.cg.shared.global [%0], [%1], 16;\n"
                 :: "r"(smem_u32(smem)), "l"(gmem));
}
__device__ __forceinline__ void mma_f16(float* c, const unsigned* a, unsigned b0, unsigned b1) {
    asm volatile(
        "mma.sync.aligned.m16n8k16.row.col.f32.f16.f16.f32 "
        "{%0,%1,%2,%3}, {%4,%5,%6,%7}, {%8,%9}, {%0,%1,%2,%3};\n"
        : "+f"(c[0]), "+f"(c[1]), "+f"(c[2]), "+f"(c[3])
        : "r"(a[0]), "r"(a[1]), "r"(a[2]), "r"(a[3]), "r"(b0), "r"(b1));
}
__device__ __forceinline__ unsigned pack_h2(float a0, float a1) {
    __half2 h = __floats2half2_rn(a0, a1);
    return *reinterpret_cast<unsigned*>(&h);
}

// ---------------- K0: fused prep (conv | qq | Bfrag) -------------------------
// blocks [0,512): conv  (b = bx>>3, t0 = (bx&7)*256, 256 threads = 256 t)
// blocks [512,640): qq  (idx = bx-512: b = idx>>1, half = idx&1 -> 64 outputs)
// blocks [640,712): Bfrag (18 chunks of fp16 fragments, zero-padded)
__global__ __launch_bounds__(256) void k_prep(
    const float* __restrict__ query, const float* __restrict__ Wq,
    const float* __restrict__ bq, const float* __restrict__ bm,
    const float* __restrict__ Wm, const float* __restrict__ Wloc,
    const float* __restrict__ aw, const float* __restrict__ Wconv) {
    int bx = blockIdx.x, tid = threadIdx.x;
    if (bx < 512) {
        __shared__ float s_aw[2][256 + KW - 1];
        __shared__ float s_w[NF * 2 * KW];
        int b = bx >> 3, t0 = (bx & 7) * 256;
        for (int i = tid; i < NF * 2 * KW; i += 256) s_w[i] = Wconv[i];
        for (int c = 0; c < 2; c++)
            for (int i = tid; i < 256 + KW - 1; i += 256) {
                int t = t0 - PADW + i;
                s_aw[c][i] = (t >= 0 && t < T) ? aw[((size_t)b * 2 + c) * T + t] : 0.f;
            }
        __syncthreads();
        float out[NF];
        #pragma unroll 4
        for (int f = 0; f < NF; f++) {
            float acc = 0.f;
            #pragma unroll
            for (int c = 0; c < 2; c++)
                #pragma unroll
                for (int k = 0; k < KW; k++)
                    acc += s_aw[c][tid + k] * s_w[(f * 2 + c) * KW + k];
            out[f] = acc;
        }
        float4* dst = (float4*)&g_conv[b][t0 + tid][0];
        #pragma unroll
        for (int j = 0; j < NF / 4; j++)
            dst[j] = make_float4(out[4 * j], out[4 * j + 1], out[4 * j + 2], out[4 * j + 3]);
    } else if (bx < 640) {
        __shared__ float4 sq[DL / 4];
        int idx = bx - 512;
        int b = idx >> 1, half = idx & 1;
        for (int i = tid; i < DL / 4; i += 256)
            sq[i] = ((const float4*)(query + (size_t)b * DL))[i];
        __syncthreads();
        int w = tid >> 5, lane = tid & 31;
        int a0 = half * 64 + w * 8;
        #pragma unroll
        for (int j = 0; j < 8; j++) {
            int a = a0 + j;
            const float4* wr = (const float4*)(Wq + (size_t)a * DL);
            float s = 0.f;
            #pragma unroll
            for (int k = 0; k < DL / 128; k++) {
                float4 q4 = sq[lane + 32 * k];
                float4 w4 = wr[lane + 32 * k];
                s += q4.x * w4.x + q4.y * w4.y + q4.z * w4.z + q4.w * w4.w;
            }
            #pragma unroll
            for (int o = 16; o; o >>= 1) s += __shfl_xor_sync(0xffffffffu, s, o);
            if (lane == 0) g_qq[b][a] = s + bq[a] + bm[a];
        }
    } else {
        int idx = (bx - 640) * 256 + tid;            // one per (ch, s, nt, lane)
        int lane = idx & 31, nt = (idx >> 5) & 15, s = (idx >> 9) & 1, ch = idx >> 10;
        int g = lane >> 2, t = lane & 3;
        int n = nt * 8 + g;
        int k0 = ch * CK + s * 16;
        float v[4];
        #pragma unroll
        for (int j = 0; j < 4; j++) {
            int k = k0 + ((j >> 1) ? (2 * t + 8) : (2 * t)) + (j & 1);
            v[j] = (k < DE) ? Wm[(size_t)n * DE + k]
                 : (k < KC) ? Wloc[n * NF + (k - DE)] : 0.f;
        }
        g_Bfrag[idx] = make_uint2(pack_h2(v[0], v[1]), pack_h2(v[2], v[3]));
    }
}

// ---------------- K3: fused S=[mem|conv]·Wcat -> tanh -> e -> flash partial ---
// CTA = one (b, 64-t tile): 64x128x576 fp16 GEMM + per-tile softmax partials +
// partial context GEMV. 256 threads, 8 warps (2M x 4N), 3 CTAs/SM.
// 4 stages, 2 chunks per __syncthreads (9 barriers instead of 17).
__global__ __launch_bounds__(256, 3) void k_main(const float* __restrict__ mem,
                                                 const float* __restrict__ Wv,
                                                 const float* __restrict__ bv) {
    extern __shared__ __align__(16) char dsm[];
    __shared__ float s_qq[DA], s_wv[DA], s_esum[TM], sp[TM];
    __shared__ float s_ml;

    int tid = threadIdx.x, lane = tid & 31, w = tid >> 5;
    int g = lane >> 2, t4 = lane & 3;
    int wM = w & 1, wN = w >> 1;                     // 2 x 4 warps
    int tx = blockIdx.x, b = blockIdx.y;
    int t0 = tx * TM;
    float bv0 = bv[0];

    if (tid < DA) { s_qq[tid] = g_qq[b][tid]; s_wv[tid] = Wv[tid]; }
    if (tid >= 128 && tid < 128 + TM) s_esum[tid - 128] = 0.f;

    const float* memB = mem + ((size_t)b * T + t0) * DE;
    int arow = tid >> 2, aq = tid & 3;               // A slot: 8 cols per thread

    // ldmatrix row pointer pieces (per lane, per mt): quadrant layout
    int lmq = lane >> 3, lmr = lane & 7;
    int lmrow_base = wM * 32 + lmr + (lmq & 1) * 8;  // + mt*16
    int lmword = (lmq >> 1) * 4;                     // + s*8

    float acc[2][4][4];
    #pragma unroll
    for (int mt = 0; mt < 2; mt++)
        #pragma unroll
        for (int nt = 0; nt < 4; nt++)
            #pragma unroll
            for (int j = 0; j < 4; j++) acc[mt][nt][j] = 0.f;

    // ---- helpers ----
    auto ldA = [&](int ch, float4* v) {
        int kk0 = ch * CK + aq * 8;
        if (kk0 < DE) {
            const float4* src = (const float4*)(memB + (size_t)arow * DE + kk0);
            v[0] = src[0]; v[1] = src[1];
        } else if (kk0 < KC) {
            const float4* src = (const float4*)(&g_conv[b][t0 + arow][kk0 - DE]);
            v[0] = src[0]; v[1] = src[1];
        } else {
            v[0] = make_float4(0.f, 0.f, 0.f, 0.f);
            v[1] = make_float4(0.f, 0.f, 0.f, 0.f);
        }
    };
    auto stA = [&](int buf, const float4* v) {
        unsigned* st = (unsigned*)(dsm + buf * STAGE);
        unsigned h0 = pack_h2(v[0].x, v[0].y), h1 = pack_h2(v[0].z, v[0].w);
        unsigned h2 = pack_h2(v[1].x, v[1].y), h3 = pack_h2(v[1].z, v[1].w);
        *(uint4*)(st + arow * A_STRIDE_W + aq * 4) = make_uint4(h0, h1, h2, h3);
    };
    auto ldB = [&](int ch, int buf) {                // no commit
        char* bb = dsm + buf * STAGE + A_PLANE;
        const char* src = (const char*)&g_Bfrag[ch * 1024];
        cpasync16(bb + tid * 16, src + tid * 16);
        cpasync16(bb + (tid + 256) * 16, src + (tid + 256) * 16);
    };
    auto mma_chunk = [&](int buf) {
        unsigned abase = smem_u32(dsm + buf * STAGE);
        const uint2* Bf = (const uint2*)(dsm + buf * STAGE + A_PLANE);
        #pragma unroll
        for (int s = 0; s < 2; s++) {
            unsigned af[2][4];
            #pragma unroll
            for (int mt = 0; mt < 2; mt++) {
                unsigned addr = abase +
                    (((lmrow_base + mt * 16) * A_STRIDE_W) + (s * 8 + lmword)) * 4;
                asm volatile(
                    "ldmatrix.sync.aligned.m8n8.x4.shared.b16 {%0,%1,%2,%3}, [%4];"
                    : "=r"(af[mt][0]), "=r"(af[mt][1]), "=r"(af[mt][2]), "=r"(af[mt][3])
                    : "r"(addr));
            }
            #pragma unroll
            for (int nt = 0; nt < 4; nt++) {
                uint2 bf = Bf[(s * 16 + wN * 4 + nt) * 32 + lane];
                #pragma unroll
                for (int mt = 0; mt < 2; mt++)
                    mma_f16(acc[mt][nt], af[mt], bf.x, bf.y);
            }
        }
    };

    // ---- prologue: chunks 0,1 into stages 0,1 ----
    {
        float4 v0[2], v1[2];
        ldA(0, v0);
        ldA(1, v1);
        ldB(0, 0);
        ldB(1, 1);
        asm volatile("cp.async.commit_group;\n");
        stA(0, v0);
        stA(1, v1);
        asm volatile("cp.async.wait_group 0;\n");
    }
    __syncthreads();

    // ---- main loop: 9 iterations x 2 chunks; prefetch next pair ----
    for (int it = 0; it < NITER; it++) {
        int buf = (it & 1) << 1;                     // current pair stages {buf, buf+1}
        int nbuf = buf ^ 2;                          // next pair
        bool pre = (it + 1) < NITER;
        int ch0 = 2 * it;
        float4 v[2];

        if (pre) {
            ldA(ch0 + 2, v);
            ldB(ch0 + 2, nbuf);
            ldB(ch0 + 3, nbuf + 1);
            asm volatile("cp.async.commit_group;\n");
        }
        mma_chunk(buf);
        if (pre) {
            stA(nbuf, v);
            ldA(ch0 + 3, v);
        }
        mma_chunk(buf + 1);
        if (pre) {
            stA(nbuf + 1, v);
            asm volatile("cp.async.wait_group 0;\n");
        }
        __syncthreads();
    }

    // ---- e[t] = bv + sum_a Wv[a]*tanh(acc + qq[a]) ----
    #pragma unroll
    for (int mt = 0; mt < 2; mt++) {
        #pragma unroll
        for (int half = 0; half < 2; half++) {
            int rloc = wM * 32 + mt * 16 + g + 8 * half;
            float p = 0.f;
            #pragma unroll
            for (int nt = 0; nt < 4; nt++) {
                int c0 = wN * 32 + nt * 8 + 2 * t4;
                float x0 = acc[mt][nt][2 * half + 0] + s_qq[c0];
                float x1 = acc[mt][nt][2 * half + 1] + s_qq[c0 + 1];
                float e0 = __expf(2.f * x0), e1 = __expf(2.f * x1);
                p += s_wv[c0]     * (1.f - __fdividef(2.f, e0 + 1.f));
                p += s_wv[c0 + 1] * (1.f - __fdividef(2.f, e1 + 1.f));
            }
            p += __shfl_xor_sync(0xffffffffu, p, 1);
            p += __shfl_xor_sync(0xffffffffu, p, 2);
            if (t4 == 0) atomicAdd(&s_esum[rloc], p);
        }
    }
    __syncthreads();

    // ---- flash partials: m_l, p_t, s_l, partial ctx ----
    if (tid < 32) {
        float m = fmaxf(s_esum[tid], s_esum[tid + 32]);
        #pragma unroll
        for (int o = 16; o; o >>= 1) m = fmaxf(m, __shfl_xor_sync(0xffffffffu, m, o));
        if (tid == 0) s_ml = m;
    }
    if (tid < TM) g_e[b][t0 + tid] = s_esum[tid] + bv0;
    __syncthreads();
    if (tid < TM) sp[tid] = __expf(s_esum[tid] - s_ml);
    __syncthreads();
    if (tid < 32) {
        float ssum = sp[tid] + sp[tid + 32];
        #pragma unroll
        for (int o = 16; o; o >>= 1) ssum += __shfl_xor_sync(0xffffffffu, ssum, o);
        if (tid == 0) g_ms[b * NTILE + tx] = make_float2(s_ml, ssum);
    }
    // partial context: pctx[d] = sum_t sp[t] * mem[t][d]  (tile is L2-hot)
    {
        const float2* mp2 = (const float2*)memB + tid;    // d = 2*tid, 2*tid+1
        float c0 = 0.f, c1 = 0.f;
        #pragma unroll 8
        for (int t = 0; t < TM; t++) {
            float wt = sp[t];
            float2 m2 = mp2[(size_t)t * (DE / 2)];
            c0 += wt * m2.x;
            c1 += wt * m2.y;
        }
        *(float2*)&g_pctx[((size_t)b * NTILE + tx) * DE + 2 * tid] = make_float2(c0, c1);
    }
}

// ---------------- K4: blocks 0..63 softmax -> out_w; 64..127 combine ctx -----
__global__ __launch_bounds__(512) void k_fin(float* __restrict__ out_w,
                                             float* __restrict__ out_ctx) {
    __shared__ float red[512];
    int tid = threadIdx.x;
    if (blockIdx.x < B) {
        int b = blockIdx.x;
        float v[4];
        float m = -1e30f;
        #pragma unroll
        for (int j = 0; j < 4; j++) { v[j] = g_e[b][tid + 512 * j]; m = fmaxf(m, v[j]); }
        red[tid] = m; __syncthreads();
        for (int s = 256; s; s >>= 1) { if (tid < s) red[tid] = fmaxf(red[tid], red[tid + s]); __syncthreads(); }
        m = red[0]; __syncthreads();
        float sum = 0.f;
        #pragma unroll
        for (int j = 0; j < 4; j++) { v[j] = expf(v[j] - m); sum += v[j]; }
        red[tid] = sum; __syncthreads();
        for (int s = 256; s; s >>= 1) { if (tid < s) red[tid] += red[tid + s]; __syncthreads(); }
        float inv = 1.f / red[0];
        #pragma unroll
        for (int j = 0; j < 4; j++) out_w[(size_t)b * T + tid + 512 * j] = v[j] * inv;
    } else {
        int b = blockIdx.x - B;
        __shared__ float sm[NTILE], ss[NTILE];
        if (tid < NTILE) {
            float2 v = g_ms[b * NTILE + tid];
            sm[tid] = v.x; ss[tid] = v.y;
        }
        __syncthreads();
        float mg = -1e30f;
        #pragma unroll
        for (int l = 0; l < NTILE; l++) mg = fmaxf(mg, sm[l]);
        float Sg = 0.f;
        float sc[NTILE];
        #pragma unroll
        for (int l = 0; l < NTILE; l++) { sc[l] = expf(sm[l] - mg); Sg += ss[l] * sc[l]; }
        float invS = 1.f / Sg;
        float acc = 0.f;
        #pragma unroll
        for (int l = 0; l < NTILE; l++)
            acc += sc[l] * g_pctx[((size_t)b * NTILE + l) * DE + tid];
        out_ctx[(size_t)b * DE + tid] = acc * invS;
    }
}

// ---------------- launch ------------------------------------------------------
extern "C" void kernel_launch(void* const* d_in, const int* in_sizes, int n_in,
                              void* d_out, int out_size) {
    const float* query  = (const float*)d_in[0];
    const float* memory = (const float*)d_in[1];
    const float* aw     = (const float*)d_in[2];
    const float* Wq     = (const float*)d_in[3];
    const float* bq     = (const float*)d_in[4];
    const float* Wm     = (const float*)d_in[5];
    const float* bm     = (const float*)d_in[6];
    const float* Wconv  = (const float*)d_in[7];
    const float* Wloc   = (const float*)d_in[8];
    const float* Wv     = (const float*)d_in[9];
    const float* bv     = (const float*)d_in[10];

    float* out_ctx = (float*)d_out;            // [B][DE]
    float* out_w   = (float*)d_out + B * DE;   // [B][T]

    cudaFuncSetAttribute(k_main, cudaFuncAttributeMaxDynamicSharedMemorySize, DSM_BYTES);

    k_prep <<<712, 256>>>(query, Wq, bq, bm, Wm, Wloc, aw, Wconv);
    k_main <<<dim3(NTILE, B), 256, DSM_BYTES>>>(memory, Wv, bv);
    k_fin  <<<2 * B, 512>>>(out_w, out_ctx);
}

// round 17
// speedup vs baseline: 1.7238x; 1.2004x over previous
#include <cuda_runtime.h>
#include <cuda_fp16.h>
#include <math.h>
#include <stdint.h>

#define B   64
#define T   2048
#define DL  1024
#define DE  512
#define DA  128
#define NF  32
#define KW  31
#define PADW 15
#define KC  (DE + NF)      // 544 (logical)
#define CK  32             // K per chunk (two m16n8k16 k-steps)
#define NCHP 18            // 16 mem chunks + 2 loc chunks (c=0,c=1; 32 taps, tap31=0)
#define NITER 9            // 2 chunks per iteration
#define TM  64             // rows per CTA tile
#define NTILE (T / TM)     // 32 tiles per batch

// dynamic smem stage layout (bytes)
#define A_STRIDE_W 20                  // words per A row (16 data + 4 pad) -> conflict-free
#define A_PLANE    (TM * A_STRIDE_W * 4)    // 5120
#define B_FRAG_BYTES (2 * 16 * 32 * 8) // 8192
#define STAGE (A_PLANE + B_FRAG_BYTES) // 13312
#define NSTAGE 4
#define DSM_BYTES (NSTAGE * STAGE)     // 53248 (opt-in)

// ---------------- scratch (static device memory; no allocations) -------------
__device__ __align__(16) float g_qq[B][DA];           // query proj + bq + bm
__device__ __align__(16) float g_e[B][T];             // energies
__device__ __align__(16) uint2 g_Bfrag[NCHP * 2 * 16 * 32];  // [Wm | Wfused] fp16 frags
__device__ __align__(16) float g_pctx[B * NTILE * DE];  // per-tile partial contexts
__device__ __align__(16) float2 g_ms[B * NTILE];        // per-tile (max, sumexp)

// ---------------- helpers ----------------------------------------------------
__device__ __forceinline__ unsigned smem_u32(const void* p) {
    return (unsigned)__cvta_generic_to_shared(p);
}
__device__ __forceinline__ void cpasync16(void* smem, const void* gmem) {
    asm volatile("cp.async.cg.shared.global [%0], [%1], 16;\n"
                 :: "r"(smem_u32(smem)), "l"(gmem));
}
__device__ __forceinline__ void mma_f16(float* c, const unsigned* a, unsigned b0, unsigned b1) {
    asm volatile(
        "mma.sync.aligned.m16n8k16.row.col.f32.f16.f16.f32 "
        "{%0,%1,%2,%3}, {%4,%5,%6,%7}, {%8,%9}, {%0,%1,%2,%3};\n"
        : "+f"(c[0]), "+f"(c[1]), "+f"(c[2]), "+f"(c[3])
        : "r"(a[0]), "r"(a[1]), "r"(a[2]), "r"(a[3]), "r"(b0), "r"(b1));
}
__device__ __forceinline__ unsigned pack_h2(float a0, float a1) {
    __half2 h = __floats2half2_rn(a0, a1);
    return *reinterpret_cast<unsigned*>(&h);
}

// ---------------- K0: fused prep (qq | Bfrag incl. Wfused) -------------------
// blocks [0,128): qq  (idx: b = idx>>1, half = idx&1 -> 64 outputs each)
// blocks [128,200): Bfrag: k<512 -> Wm; k>=512 -> Wfused[(c,tap),n] =
//                   sum_f Wconv[f,c,tap]*Wloc[n,f]  (tap 31 = 0)
__global__ __launch_bounds__(256) void k_prep(
    const float* __restrict__ query, const float* __restrict__ Wq,
    const float* __restrict__ bq, const float* __restrict__ bm,
    const float* __restrict__ Wm, const float* __restrict__ Wloc,
    const float* __restrict__ Wconv) {
    int bx = blockIdx.x, tid = threadIdx.x;
    if (bx < 128) {
        __shared__ float4 sq[DL / 4];
        int b = bx >> 1, half = bx & 1;
        for (int i = tid; i < DL / 4; i += 256)
            sq[i] = ((const float4*)(query + (size_t)b * DL))[i];
        __syncthreads();
        int w = tid >> 5, lane = tid & 31;
        int a0 = half * 64 + w * 8;
        #pragma unroll
        for (int j = 0; j < 8; j++) {
            int a = a0 + j;
            const float4* wr = (const float4*)(Wq + (size_t)a * DL);
            float s = 0.f;
            #pragma unroll
            for (int k = 0; k < DL / 128; k++) {
                float4 q4 = sq[lane + 32 * k];
                float4 w4 = wr[lane + 32 * k];
                s += q4.x * w4.x + q4.y * w4.y + q4.z * w4.z + q4.w * w4.w;
            }
            #pragma unroll
            for (int o = 16; o; o >>= 1) s += __shfl_xor_sync(0xffffffffu, s, o);
            if (lane == 0) g_qq[b][a] = s + bq[a] + bm[a];
        }
    } else {
        int idx = (bx - 128) * 256 + tid;            // one per (ch, s, nt, lane)
        int lane = idx & 31, nt = (idx >> 5) & 15, s = (idx >> 9) & 1, ch = idx >> 10;
        int g = lane >> 2, t = lane & 3;
        int n = nt * 8 + g;
        int k0 = ch * CK + s * 16;
        float v[4];
        #pragma unroll
        for (int j = 0; j < 4; j++) {
            int k = k0 + ((j >> 1) ? (2 * t + 8) : (2 * t)) + (j & 1);
            if (k < DE) {
                v[j] = Wm[(size_t)n * DE + k];
            } else {
                int c = (k - DE) >> 5, tap = (k - DE) & 31;
                float acc = 0.f;
                if (tap < KW) {
                    #pragma unroll 8
                    for (int f = 0; f < NF; f++)
                        acc += Wconv[(f * 2 + c) * KW + tap] * Wloc[n * NF + f];
                }
                v[j] = acc;
            }
        }
        g_Bfrag[idx] = make_uint2(pack_h2(v[0], v[1]), pack_h2(v[2], v[3]));
    }
}

// ---------------- K3: fused S=[mem|aw-windows]·[Wm|Wfused] -> tanh -> e ------
// CTA = one (b, 64-t tile): 64x128x576 fp16 GEMM + per-tile softmax partials +
// partial context GEMV. 256 threads, 8 warps (2M x 4N), 3 CTAs/SM.
// 4 stages, 2 chunks per __syncthreads. Chunks 16,17: A = shifted aw windows.
__global__ __launch_bounds__(256, 3) void k_main(const float* __restrict__ mem,
                                                 const float* __restrict__ aw,
                                                 const float* __restrict__ Wv,
                                                 const float* __restrict__ bv) {
    extern __shared__ __align__(16) char dsm[];
    __shared__ float s_qq[DA], s_wv[DA], s_esum[TM], sp[TM];
    __shared__ float s_ml;

    int tid = threadIdx.x, lane = tid & 31, w = tid >> 5;
    int g = lane >> 2, t4 = lane & 3;
    int wM = w & 1, wN = w >> 1;                     // 2 x 4 warps
    int tx = blockIdx.x, b = blockIdx.y;
    int t0 = tx * TM;
    float bv0 = bv[0];

    if (tid < DA) { s_qq[tid] = g_qq[b][tid]; s_wv[tid] = Wv[tid]; }
    if (tid >= 128 && tid < 128 + TM) s_esum[tid - 128] = 0.f;

    const float* memB = mem + ((size_t)b * T + t0) * DE;
    int arow = tid >> 2, aq = tid & 3;               // A slot: 8 cols per thread

    // ldmatrix row pointer pieces (per lane, per mt): quadrant layout
    int lmq = lane >> 3, lmr = lane & 7;
    int lmrow_base = wM * 32 + lmr + (lmq & 1) * 8;  // + mt*16
    int lmword = (lmq >> 1) * 4;                     // + s*8

    float acc[2][4][4];
    #pragma unroll
    for (int mt = 0; mt < 2; mt++)
        #pragma unroll
        for (int nt = 0; nt < 4; nt++)
            #pragma unroll
            for (int j = 0; j < 4; j++) acc[mt][nt][j] = 0.f;

    // ---- helpers ----
    auto ldA = [&](int ch, float4* v) {
        int kk0 = ch * CK + aq * 8;
        if (kk0 < DE) {
            const float4* src = (const float4*)(memB + (size_t)arow * DE + kk0);
            v[0] = src[0]; v[1] = src[1];
        } else {
            // loc chunk: A[t][k] = aw[c][t0 + t + tap - 15], tap 31 -> 0
            int c = (kk0 - DE) >> 5;
            int tapbase = (kk0 - DE) & 31;
            const float* awc = aw + ((size_t)(2 * b + c)) * T;
            float tmp[8];
            #pragma unroll
            for (int i = 0; i < 8; i++) {
                int tap = tapbase + i;
                int tg = t0 + arow + tap - PADW;
                tmp[i] = (tap < KW && tg >= 0 && tg < T) ? __ldg(awc + tg) : 0.f;
            }
            v[0] = make_float4(tmp[0], tmp[1], tmp[2], tmp[3]);
            v[1] = make_float4(tmp[4], tmp[5], tmp[6], tmp[7]);
        }
    };
    auto stA = [&](int buf, const float4* v) {
        unsigned* st = (unsigned*)(dsm + buf * STAGE);
        unsigned h0 = pack_h2(v[0].x, v[0].y), h1 = pack_h2(v[0].z, v[0].w);
        unsigned h2 = pack_h2(v[1].x, v[1].y), h3 = pack_h2(v[1].z, v[1].w);
        *(uint4*)(st + arow * A_STRIDE_W + aq * 4) = make_uint4(h0, h1, h2, h3);
    };
    auto ldB = [&](int ch, int buf) {                // no commit
        char* bb = dsm + buf * STAGE + A_PLANE;
        const char* src = (const char*)&g_Bfrag[ch * 1024];
        cpasync16(bb + tid * 16, src + tid * 16);
        cpasync16(bb + (tid + 256) * 16, src + (tid + 256) * 16);
    };
    auto mma_chunk = [&](int buf) {
        unsigned abase = smem_u32(dsm + buf * STAGE);
        const uint2* Bf = (const uint2*)(dsm + buf * STAGE + A_PLANE);
        #pragma unroll
        for (int s = 0; s < 2; s++) {
            unsigned af[2][4];
            #pragma unroll
            for (int mt = 0; mt < 2; mt++) {
                unsigned addr = abase +
                    (((lmrow_base + mt * 16) * A_STRIDE_W) + (s * 8 + lmword)) * 4;
                asm volatile(
                    "ldmatrix.sync.aligned.m8n8.x4.shared.b16 {%0,%1,%2,%3}, [%4];"
                    : "=r"(af[mt][0]), "=r"(af[mt][1]), "=r"(af[mt][2]), "=r"(af[mt][3])
                    : "r"(addr));
            }
            #pragma unroll
            for (int nt = 0; nt < 4; nt++) {
                uint2 bf = Bf[(s * 16 + wN * 4 + nt) * 32 + lane];
                #pragma unroll
                for (int mt = 0; mt < 2; mt++)
                    mma_f16(acc[mt][nt], af[mt], bf.x, bf.y);
            }
        }
    };

    // ---- prologue: chunks 0,1 into stages 0,1 ----
    {
        float4 v0[2], v1[2];
        ldA(0, v0);
        ldA(1, v1);
        ldB(0, 0);
        ldB(1, 1);
        asm volatile("cp.async.commit_group;\n");
        stA(0, v0);
        stA(1, v1);
        asm volatile("cp.async.wait_group 0;\n");
    }
    __syncthreads();

    // ---- main loop: 9 iterations x 2 chunks; prefetch next pair ----
    for (int it = 0; it < NITER; it++) {
        int buf = (it & 1) << 1;                     // current pair stages {buf, buf+1}
        int nbuf = buf ^ 2;                          // next pair
        bool pre = (it + 1) < NITER;
        int ch0 = 2 * it;
        float4 v[2];

        if (pre) {
            ldA(ch0 + 2, v);
            ldB(ch0 + 2, nbuf);
            ldB(ch0 + 3, nbuf + 1);
            asm volatile("cp.async.commit_group;\n");
        }
        mma_chunk(buf);
        if (pre) {
            stA(nbuf, v);
            ldA(ch0 + 3, v);
        }
        mma_chunk(buf + 1);
        if (pre) {
            stA(nbuf + 1, v);
            asm volatile("cp.async.wait_group 0;\n");
        }
        __syncthreads();
    }

    // ---- e[t] = bv + sum_a Wv[a]*tanh(acc + qq[a]) ----
    #pragma unroll
    for (int mt = 0; mt < 2; mt++) {
        #pragma unroll
        for (int half = 0; half < 2; half++) {
            int rloc = wM * 32 + mt * 16 + g + 8 * half;
            float p = 0.f;
            #pragma unroll
            for (int nt = 0; nt < 4; nt++) {
                int c0 = wN * 32 + nt * 8 + 2 * t4;
                float x0 = acc[mt][nt][2 * half + 0] + s_qq[c0];
                float x1 = acc[mt][nt][2 * half + 1] + s_qq[c0 + 1];
                float e0 = __expf(2.f * x0), e1 = __expf(2.f * x1);
                p += s_wv[c0]     * (1.f - __fdividef(2.f, e0 + 1.f));
                p += s_wv[c0 + 1] * (1.f - __fdividef(2.f, e1 + 1.f));
            }
            p += __shfl_xor_sync(0xffffffffu, p, 1);
            p += __shfl_xor_sync(0xffffffffu, p, 2);
            if (t4 == 0) atomicAdd(&s_esum[rloc], p);
        }
    }
    __syncthreads();

    // ---- flash partials: m_l, p_t, s_l, partial ctx ----
    if (tid < 32) {
        float m = fmaxf(s_esum[tid], s_esum[tid + 32]);
        #pragma unroll
        for (int o = 16; o; o >>= 1) m = fmaxf(m, __shfl_xor_sync(0xffffffffu, m, o));
        if (tid == 0) s_ml = m;
    }
    if (tid < TM) g_e[b][t0 + tid] = s_esum[tid] + bv0;
    __syncthreads();
    if (tid < TM) sp[tid] = __expf(s_esum[tid] - s_ml);
    __syncthreads();
    if (tid < 32) {
        float ssum = sp[tid] + sp[tid + 32];
        #pragma unroll
        for (int o = 16; o; o >>= 1) ssum += __shfl_xor_sync(0xffffffffu, ssum, o);
        if (tid == 0) g_ms[b * NTILE + tx] = make_float2(s_ml, ssum);
    }
    // partial context: pctx[d] = sum_t sp[t] * mem[t][d]  (tile is L2-hot)
    {
        const float2* mp2 = (const float2*)memB + tid;    // d = 2*tid, 2*tid+1
        float c0 = 0.f, c1 = 0.f;
        #pragma unroll 8
        for (int t = 0; t < TM; t++) {
            float wt = sp[t];
            float2 m2 = mp2[(size_t)t * (DE / 2)];
            c0 += wt * m2.x;
            c1 += wt * m2.y;
        }
        *(float2*)&g_pctx[((size_t)b * NTILE + tx) * DE + 2 * tid] = make_float2(c0, c1);
    }
}

// ---------------- K4: blocks 0..63 softmax -> out_w; 64..127 combine ctx -----
__global__ __launch_bounds__(512) void k_fin(float* __restrict__ out_w,
                                             float* __restrict__ out_ctx) {
    __shared__ float red[512];
    int tid = threadIdx.x;
    if (blockIdx.x < B) {
        int b = blockIdx.x;
        float v[4];
        float m = -1e30f;
        #pragma unroll
        for (int j = 0; j < 4; j++) { v[j] = g_e[b][tid + 512 * j]; m = fmaxf(m, v[j]); }
        red[tid] = m; __syncthreads();
        for (int s = 256; s; s >>= 1) { if (tid < s) red[tid] = fmaxf(red[tid], red[tid + s]); __syncthreads(); }
        m = red[0]; __syncthreads();
        float sum = 0.f;
        #pragma unroll
        for (int j = 0; j < 4; j++) { v[j] = expf(v[j] - m); sum += v[j]; }
        red[tid] = sum; __syncthreads();
        for (int s = 256; s; s >>= 1) { if (tid < s) red[tid] += red[tid + s]; __syncthreads(); }
        float inv = 1.f / red[0];
        #pragma unroll
        for (int j = 0; j < 4; j++) out_w[(size_t)b * T + tid + 512 * j] = v[j] * inv;
    } else {
        int b = blockIdx.x - B;
        __shared__ float sm[NTILE], ss[NTILE];
        if (tid < NTILE) {
            float2 v = g_ms[b * NTILE + tid];
            sm[tid] = v.x; ss[tid] = v.y;
        }
        __syncthreads();
        float mg = -1e30f;
        #pragma unroll
        for (int l = 0; l < NTILE; l++) mg = fmaxf(mg, sm[l]);
        float Sg = 0.f;
        float sc[NTILE];
        #pragma unroll
        for (int l = 0; l < NTILE; l++) { sc[l] = expf(sm[l] - mg); Sg += ss[l] * sc[l]; }
        float invS = 1.f / Sg;
        float acc = 0.f;
        #pragma unroll
        for (int l = 0; l < NTILE; l++)
            acc += sc[l] * g_pctx[((size_t)b * NTILE + l) * DE + tid];
        out_ctx[(size_t)b * DE + tid] = acc * invS;
    }
}

// ---------------- launch ------------------------------------------------------
extern "C" void kernel_launch(void* const* d_in, const int* in_sizes, int n_in,
                              void* d_out, int out_size) {
    const float* query  = (const float*)d_in[0];
    const float* memory = (const float*)d_in[1];
    const float* aw     = (const float*)d_in[2];
    const float* Wq     = (const float*)d_in[3];
    const float* bq     = (const float*)d_in[4];
    const float* Wm     = (const float*)d_in[5];
    const float* bm     = (const float*)d_in[6];
    const float* Wconv  = (const float*)d_in[7];
    const float* Wloc   = (const float*)d_in[8];
    const float* Wv     = (const float*)d_in[9];
    const float* bv     = (const float*)d_in[10];

    float* out_ctx = (float*)d_out;            // [B][DE]
    float* out_w   = (float*)d_out + B * DE;   // [B][T]

    cudaFuncSetAttribute(k_main, cudaFuncAttributeMaxDynamicSharedMemorySize, DSM_BYTES);

    k_prep <<<200, 256>>>(query, Wq, bq, bm, Wm, Wloc, Wconv);
    k_main <<<dim3(NTILE, B), 256, DSM_BYTES>>>(memory, aw, Wv, bv);
    k_fin  <<<2 * B, 512>>>(out_w, out_ctx);
}